// round 3
// baseline (speedup 1.0000x reference)
#include <cuda_runtime.h>
#include <cuda_fp16.h>
#include <cstdint>

// Problem constants
#define NROWS   8192
#define IN_F    4096
#define OUT_F   4096
#define E_NUM   8
#define R_PER   16
#define R_TOT   128              // E_NUM * R_PER
#define KCAT    (IN_F + R_TOT)   // 4224
#define P_COLS  (E_NUM + R_TOT)  // 136
#define SCALING 0.125f           // 16 / 128

// -------- device scratch (allocation-free rule: __device__ globals) --------
__device__ __half g_Xcat[(size_t)NROWS * KCAT];     // [8192, 4224] fp16: [x | H]
__device__ __half g_Wcat[(size_t)OUT_F * KCAT];     // [4096, 4224] fp16: [W0 | Bmat]
__device__ __half g_WgA [(size_t)P_COLS * IN_F];    // [136, 4096] fp16: [Wg ; A]
__device__ float  g_P   [(size_t)NROWS * P_COLS];   // [8192, 136]: logits | h

// ---------------- conversion kernels ----------------
__global__ void conv_x_kernel(const float* __restrict__ x, __half* __restrict__ Xcat) {
    int64_t total = (int64_t)NROWS * IN_F;
    for (int64_t i = (int64_t)blockIdx.x * blockDim.x + threadIdx.x; i < total;
         i += (int64_t)gridDim.x * blockDim.x) {
        int n = (int)(i >> 12);          // /4096
        int k = (int)(i & 4095);
        Xcat[(int64_t)n * KCAT + k] = __float2half_rn(x[i]);
    }
}

__global__ void conv_w_kernel(const float* __restrict__ W0, const float* __restrict__ B,
                              __half* __restrict__ Wcat) {
    int64_t total = (int64_t)OUT_F * KCAT;
    for (int64_t i = (int64_t)blockIdx.x * blockDim.x + threadIdx.x; i < total;
         i += (int64_t)gridDim.x * blockDim.x) {
        int o = (int)(i / KCAT);
        int c = (int)(i - (int64_t)o * KCAT);
        float v;
        if (c < IN_F) {
            v = W0[(int64_t)o * IN_F + c];
        } else {
            int cc = c - IN_F;           // e*16 + r
            int e = cc >> 4, r = cc & 15;
            // B shape [E, OUT_F, R_PER]
            v = B[((int64_t)e * OUT_F + o) * R_PER + r];
        }
        Wcat[i] = __float2half_rn(v);
    }
}

__global__ void conv_wga_kernel(const float* __restrict__ Wg, const float* __restrict__ A,
                                __half* __restrict__ WgA) {
    int64_t total = (int64_t)P_COLS * IN_F;
    for (int64_t i = (int64_t)blockIdx.x * blockDim.x + threadIdx.x; i < total;
         i += (int64_t)gridDim.x * blockDim.x) {
        int j = (int)(i >> 12);          // row 0..135
        int k = (int)(i & 4095);
        float v = (j < E_NUM) ? Wg[(int64_t)j * IN_F + k]
                              : A[(int64_t)(j - E_NUM) * IN_F + k]; // A flat [E*R_PER, IN_F]
        WgA[i] = __float2half_rn(v);
    }
}

// ---------------- softmax + pack H into Xcat ----------------
__global__ void softmax_pack_kernel(const float* __restrict__ P, __half* __restrict__ Xcat) {
    int n = blockIdx.x;                  // 8192 blocks, 128 threads
    int t = threadIdx.x;
    __shared__ float gate[E_NUM];
    if (t == 0) {
        float l[E_NUM];
        float mx = -1e30f;
        #pragma unroll
        for (int e = 0; e < E_NUM; e++) { l[e] = P[(int64_t)n * P_COLS + e]; mx = fmaxf(mx, l[e]); }
        float s = 0.f;
        #pragma unroll
        for (int e = 0; e < E_NUM; e++) { l[e] = expf(l[e] - mx); s += l[e]; }
        float inv = 1.0f / s;
        #pragma unroll
        for (int e = 0; e < E_NUM; e++) gate[e] = l[e] * inv;
    }
    __syncthreads();
    // t in [0,128): H column t = e*16+r
    float h = P[(int64_t)n * P_COLS + E_NUM + t];
    int e = t >> 4;
    Xcat[(int64_t)n * KCAT + IN_F + t] = __float2half_rn(SCALING * gate[e] * h);
}

// ---------------- fp16 mma.sync GEMM:  C[M,N] = A[M,K] @ B[N,K]^T ----------------
#define BM 128
#define BN 128
#define BK 32
#define SLD 40   // BK + 8 halves padding -> conflict-free fragment LDS

__global__ __launch_bounds__(256)
void gemm_f16_kernel(const __half* __restrict__ A, const __half* __restrict__ B,
                     float* __restrict__ C,
                     int M, int N, int K, int lda, int ldb, int ldc) {
    __shared__ __half As[BM * SLD];
    __shared__ __half Bs[BN * SLD];

    const int tid  = threadIdx.x;
    const int warp = tid >> 5;
    const int lane = tid & 31;
    const int g    = lane >> 2;   // group id 0..7
    const int tg   = lane & 3;    // thread-in-group 0..3
    const int wm   = (warp & 3) * 32;   // warp M offset (4 warps along M)
    const int wn   = (warp >> 2) * 64;  // warp N offset (2 warps along N)
    const int bm   = blockIdx.y * BM;
    const int bn   = blockIdx.x * BN;

    float acc[2][8][4];
    #pragma unroll
    for (int mf = 0; mf < 2; mf++)
        #pragma unroll
        for (int nf = 0; nf < 8; nf++)
            #pragma unroll
            for (int i = 0; i < 4; i++) acc[mf][nf][i] = 0.f;

    const int lr = tid >> 2;        // 0..63
    const int lc = (tid & 3) * 8;   // 0,8,16,24 (halves)

    for (int k0 = 0; k0 < K; k0 += BK) {
        // load A tile (rows always in-bounds: M multiple of 128)
        #pragma unroll
        for (int i = 0; i < 2; i++) {
            int row = lr + i * 64;
            const int4* src = (const int4*)(A + (int64_t)(bm + row) * lda + k0 + lc);
            *(int4*)&As[row * SLD + lc] = *src;
        }
        // load B tile with N bounds check (zero-fill OOB rows)
        #pragma unroll
        for (int i = 0; i < 2; i++) {
            int row = lr + i * 64;
            int4 v;
            if (bn + row < N) v = *(const int4*)(B + (int64_t)(bn + row) * ldb + k0 + lc);
            else              v = make_int4(0, 0, 0, 0);
            *(int4*)&Bs[row * SLD + lc] = v;
        }
        __syncthreads();

        #pragma unroll
        for (int kk = 0; kk < BK; kk += 16) {
            uint32_t a[2][4], b[8][2];
            #pragma unroll
            for (int mf = 0; mf < 2; mf++) {
                int r0 = wm + mf * 16;
                a[mf][0] = *(const uint32_t*)&As[(r0 + g    ) * SLD + kk + 2 * tg    ];
                a[mf][1] = *(const uint32_t*)&As[(r0 + g + 8) * SLD + kk + 2 * tg    ];
                a[mf][2] = *(const uint32_t*)&As[(r0 + g    ) * SLD + kk + 2 * tg + 8];
                a[mf][3] = *(const uint32_t*)&As[(r0 + g + 8) * SLD + kk + 2 * tg + 8];
            }
            #pragma unroll
            for (int nf = 0; nf < 8; nf++) {
                int c0 = wn + nf * 8;
                b[nf][0] = *(const uint32_t*)&Bs[(c0 + g) * SLD + kk + 2 * tg    ];
                b[nf][1] = *(const uint32_t*)&Bs[(c0 + g) * SLD + kk + 2 * tg + 8];
            }
            #pragma unroll
            for (int mf = 0; mf < 2; mf++)
                #pragma unroll
                for (int nf = 0; nf < 8; nf++)
                    asm volatile(
                        "mma.sync.aligned.m16n8k16.row.col.f32.f16.f16.f32 "
                        "{%0,%1,%2,%3}, {%4,%5,%6,%7}, {%8,%9}, {%0,%1,%2,%3};\n"
                        : "+f"(acc[mf][nf][0]), "+f"(acc[mf][nf][1]),
                          "+f"(acc[mf][nf][2]), "+f"(acc[mf][nf][3])
                        : "r"(a[mf][0]), "r"(a[mf][1]), "r"(a[mf][2]), "r"(a[mf][3]),
                          "r"(b[nf][0]), "r"(b[nf][1]));
        }
        __syncthreads();
    }

    // epilogue
    #pragma unroll
    for (int mf = 0; mf < 2; mf++) {
        int r0 = bm + wm + mf * 16 + g;
        #pragma unroll
        for (int nf = 0; nf < 8; nf++) {
            int c = bn + wn + nf * 8 + 2 * tg;
            if (c < N) {
                C[(int64_t)r0 * ldc + c]       = acc[mf][nf][0];
                C[(int64_t)(r0 + 8) * ldc + c] = acc[mf][nf][2];
            }
            if (c + 1 < N) {
                C[(int64_t)r0 * ldc + c + 1]       = acc[mf][nf][1];
                C[(int64_t)(r0 + 8) * ldc + c + 1] = acc[mf][nf][3];
            }
        }
    }
}

// ---------------- launch ----------------
extern "C" void kernel_launch(void* const* d_in, const int* in_sizes, int n_in,
                              void* d_out, int out_size) {
    const float* x  = (const float*)d_in[0];  // [8192, 4096]
    const float* W0 = (const float*)d_in[1];  // [4096, 4096]
    const float* Wg = (const float*)d_in[2];  // [8, 4096]
    const float* A  = (const float*)d_in[3];  // [8, 16, 4096]
    const float* B  = (const float*)d_in[4];  // [8, 4096, 16]
    float* out = (float*)d_out;               // [8192, 4096]

    __half *Xcat, *Wcat, *WgA;
    float* P;
    cudaGetSymbolAddress((void**)&Xcat, g_Xcat);
    cudaGetSymbolAddress((void**)&Wcat, g_Wcat);
    cudaGetSymbolAddress((void**)&WgA,  g_WgA);
    cudaGetSymbolAddress((void**)&P,    g_P);

    conv_x_kernel  <<<4096, 256>>>(x, Xcat);
    conv_w_kernel  <<<4096, 256>>>(W0, B, Wcat);
    conv_wga_kernel<<<512,  256>>>(Wg, A, WgA);

    // P[8192,136] = x_fp16 @ [Wg;A]^T   (K = 4096, read from Xcat's first 4096 cols)
    gemm_f16_kernel<<<dim3(2, NROWS / BM), 256>>>(
        Xcat, WgA, P, NROWS, P_COLS, IN_F, KCAT, IN_F, P_COLS);

    // softmax gate, scale, pack H into Xcat[:, 4096:4224]
    softmax_pack_kernel<<<NROWS, 128>>>(P, Xcat);

    // out = [x | H] @ [W0 | Bmat]^T   (K = 4224)
    gemm_f16_kernel<<<dim3(OUT_F / BN, NROWS / BM), 256>>>(
        Xcat, Wcat, out, NROWS, OUT_F, KCAT, KCAT, KCAT, OUT_F);
}

// round 4
// speedup vs baseline: 1.4093x; 1.4093x over previous
#include <cuda_runtime.h>
#include <cuda_fp16.h>
#include <cstdint>

// Problem constants
#define NROWS   8192
#define IN_F    4096
#define OUT_F   4096
#define E_NUM   8
#define R_PER   16
#define R_TOT   128              // E_NUM * R_PER
#define KCAT    (IN_F + R_TOT)   // 4224
#define P_COLS  (E_NUM + R_TOT)  // 136
#define SCALING 0.125f           // 16 / 128

// -------- device scratch (allocation-free rule: __device__ globals) --------
__device__ __half g_Xcat[(size_t)NROWS * KCAT];     // [8192, 4224] fp16: [x | H]
__device__ __half g_Wcat[(size_t)OUT_F * KCAT];     // [4096, 4224] fp16: [W0 | Bmat]
__device__ __half g_WgA [(size_t)P_COLS * IN_F];    // [136, 4096] fp16: [Wg ; A]
__device__ float  g_P   [(size_t)NROWS * P_COLS];   // [8192, 136]: logits | h

// ---------------- conversion kernels (vectorized) ----------------
__global__ void conv_x_kernel(const float4* __restrict__ x, __half* __restrict__ Xcat) {
    int64_t total = (int64_t)NROWS * IN_F / 4;
    for (int64_t i = (int64_t)blockIdx.x * blockDim.x + threadIdx.x; i < total;
         i += (int64_t)gridDim.x * blockDim.x) {
        float4 v = x[i];
        int64_t e = i << 2;
        int n = (int)(e >> 12);
        int k = (int)(e & 4095);
        __half2 h0 = __floats2half2_rn(v.x, v.y);
        __half2 h1 = __floats2half2_rn(v.z, v.w);
        __half2* dst = (__half2*)&Xcat[(int64_t)n * KCAT + k];
        dst[0] = h0; dst[1] = h1;
    }
}

// W0 part of Wcat (vectorized copy-convert)
__global__ void conv_w0_kernel(const float4* __restrict__ W0, __half* __restrict__ Wcat) {
    int64_t total = (int64_t)OUT_F * IN_F / 4;
    for (int64_t i = (int64_t)blockIdx.x * blockDim.x + threadIdx.x; i < total;
         i += (int64_t)gridDim.x * blockDim.x) {
        float4 v = W0[i];
        int64_t e = i << 2;
        int o = (int)(e >> 12);
        int c = (int)(e & 4095);
        __half2 h0 = __floats2half2_rn(v.x, v.y);
        __half2 h1 = __floats2half2_rn(v.z, v.w);
        __half2* dst = (__half2*)&Wcat[(int64_t)o * KCAT + c];
        dst[0] = h0; dst[1] = h1;
    }
}

// Bmat part of Wcat: Wcat[o][4096 + e*16 + r] = B[e][o][r]
__global__ void conv_bmat_kernel(const float* __restrict__ B, __half* __restrict__ Wcat) {
    int64_t total = (int64_t)OUT_F * R_TOT;
    for (int64_t i = (int64_t)blockIdx.x * blockDim.x + threadIdx.x; i < total;
         i += (int64_t)gridDim.x * blockDim.x) {
        int o  = (int)(i >> 7);       // /128
        int cc = (int)(i & 127);      // e*16 + r
        int e = cc >> 4, r = cc & 15;
        float v = B[((int64_t)e * OUT_F + o) * R_PER + r];
        Wcat[(int64_t)o * KCAT + IN_F + cc] = __float2half_rn(v);
    }
}

__global__ void conv_wga_kernel(const float* __restrict__ Wg, const float* __restrict__ A,
                                __half* __restrict__ WgA) {
    int64_t total = (int64_t)P_COLS * IN_F;
    for (int64_t i = (int64_t)blockIdx.x * blockDim.x + threadIdx.x; i < total;
         i += (int64_t)gridDim.x * blockDim.x) {
        int j = (int)(i >> 12);
        int k = (int)(i & 4095);
        float v = (j < E_NUM) ? Wg[(int64_t)j * IN_F + k]
                              : A[(int64_t)(j - E_NUM) * IN_F + k];
        WgA[i] = __float2half_rn(v);
    }
}

// ---------------- softmax + pack H into Xcat ----------------
__global__ void softmax_pack_kernel(const float* __restrict__ P, __half* __restrict__ Xcat) {
    int n = blockIdx.x;
    int t = threadIdx.x;
    __shared__ float gate[E_NUM];
    if (t == 0) {
        float l[E_NUM];
        float mx = -1e30f;
        #pragma unroll
        for (int e = 0; e < E_NUM; e++) { l[e] = P[(int64_t)n * P_COLS + e]; mx = fmaxf(mx, l[e]); }
        float s = 0.f;
        #pragma unroll
        for (int e = 0; e < E_NUM; e++) { l[e] = expf(l[e] - mx); s += l[e]; }
        float inv = 1.0f / s;
        #pragma unroll
        for (int e = 0; e < E_NUM; e++) gate[e] = l[e] * inv;
    }
    __syncthreads();
    float h = P[(int64_t)n * P_COLS + E_NUM + t];
    int e = t >> 4;
    Xcat[(int64_t)n * KCAT + IN_F + t] = __float2half_rn(SCALING * gate[e] * h);
}

// ---------------- fp16 mma.sync GEMM, cp.async double-buffered + ldmatrix ----------------
// C[M,N] = A[M,K] @ B[N,K]^T
#define BM 128
#define BN 128
#define BK 32
#define SLD 40   // BK + 8 halves padding (80B rows -> ldmatrix phase conflict-free)

__device__ __forceinline__ uint32_t smem_u32(const void* p) {
    return (uint32_t)__cvta_generic_to_shared(p);
}
__device__ __forceinline__ void cp16(uint32_t dst, const void* src, bool pred) {
    int sz = pred ? 16 : 0;   // src-size 0 -> zero-fill, no gmem access
    asm volatile("cp.async.cg.shared.global [%0], [%1], 16, %2;\n"
                 :: "r"(dst), "l"(src), "r"(sz));
}
__device__ __forceinline__ void ldsm_x4(uint32_t& r0, uint32_t& r1, uint32_t& r2, uint32_t& r3,
                                        uint32_t addr) {
    asm volatile("ldmatrix.sync.aligned.m8n8.x4.shared.b16 {%0,%1,%2,%3}, [%4];\n"
                 : "=r"(r0), "=r"(r1), "=r"(r2), "=r"(r3) : "r"(addr));
}

__global__ __launch_bounds__(256, 2)
void gemm_f16_pipe(const __half* __restrict__ A, const __half* __restrict__ B,
                   float* __restrict__ C,
                   int M, int N, int K, int lda, int ldb, int ldc) {
    __shared__ __half As[2][BM * SLD];
    __shared__ __half Bs[2][BN * SLD];

    const int tid  = threadIdx.x;
    const int warp = tid >> 5;
    const int lane = tid & 31;
    const int g    = lane >> 2;
    const int tg   = lane & 3;
    const int lm   = lane & 7;          // ldmatrix row-within-matrix
    const int wm   = (warp & 3) * 32;   // 4 warps along M
    const int wn   = (warp >> 2) * 64;  // 2 warps along N
    const int bm   = blockIdx.y * BM;
    const int bn   = blockIdx.x * BN;

    const int lr = tid >> 2;            // 0..63 (load row)
    const int lc = (tid & 3) * 8;       // load col in halves

    float acc[2][8][4];
    #pragma unroll
    for (int mf = 0; mf < 2; mf++)
        #pragma unroll
        for (int nf = 0; nf < 8; nf++)
            #pragma unroll
            for (int i = 0; i < 4; i++) acc[mf][nf][i] = 0.f;

    const int nt = K / BK;

    // ldmatrix address offsets (within a stage)
    const int a_row_off = ((lane >> 3) & 1) * 8 + lm;   // +0/+8 row, by matrix idx
    const int a_col_off = (lane >> 4) * 8;              // +0/+8 in k
    const int b_row_off = (lane >> 4) * 8 + lm;         // +0/+8 col(n)
    const int b_col_off = ((lane >> 3) & 1) * 8;        // +0/+8 in k

    auto load_stage = [&](int s, int k0) {
        #pragma unroll
        for (int i = 0; i < 2; i++) {
            int row = lr + i * 64;
            cp16(smem_u32(&As[s][row * SLD + lc]),
                 A + (int64_t)(bm + row) * lda + k0 + lc, true);
        }
        #pragma unroll
        for (int i = 0; i < 2; i++) {
            int row = lr + i * 64;
            cp16(smem_u32(&Bs[s][row * SLD + lc]),
                 B + (int64_t)(bn + row) * ldb + k0 + lc, (bn + row) < N);
        }
        asm volatile("cp.async.commit_group;\n");
    };

    load_stage(0, 0);

    for (int t = 0; t < nt; t++) {
        const int s = t & 1;
        if (t + 1 < nt) {
            load_stage(s ^ 1, (t + 1) * BK);
            asm volatile("cp.async.wait_group 1;\n");
        } else {
            asm volatile("cp.async.wait_group 0;\n");
        }
        __syncthreads();

        #pragma unroll
        for (int kk = 0; kk < BK; kk += 16) {
            uint32_t a[2][4], b[8][2];
            #pragma unroll
            for (int mf = 0; mf < 2; mf++) {
                uint32_t addr = smem_u32(
                    &As[s][(wm + mf * 16 + a_row_off) * SLD + kk + a_col_off]);
                ldsm_x4(a[mf][0], a[mf][1], a[mf][2], a[mf][3], addr);
            }
            #pragma unroll
            for (int p = 0; p < 4; p++) {
                uint32_t addr = smem_u32(
                    &Bs[s][(wn + p * 16 + b_row_off) * SLD + kk + b_col_off]);
                ldsm_x4(b[2 * p][0], b[2 * p][1], b[2 * p + 1][0], b[2 * p + 1][1], addr);
            }
            #pragma unroll
            for (int mf = 0; mf < 2; mf++)
                #pragma unroll
                for (int nf = 0; nf < 8; nf++)
                    asm volatile(
                        "mma.sync.aligned.m16n8k16.row.col.f32.f16.f16.f32 "
                        "{%0,%1,%2,%3}, {%4,%5,%6,%7}, {%8,%9}, {%0,%1,%2,%3};\n"
                        : "+f"(acc[mf][nf][0]), "+f"(acc[mf][nf][1]),
                          "+f"(acc[mf][nf][2]), "+f"(acc[mf][nf][3])
                        : "r"(a[mf][0]), "r"(a[mf][1]), "r"(a[mf][2]), "r"(a[mf][3]),
                          "r"(b[nf][0]), "r"(b[nf][1]));
        }
        __syncthreads();
    }

    // epilogue (vectorized float2 stores)
    #pragma unroll
    for (int mf = 0; mf < 2; mf++) {
        int r0 = bm + wm + mf * 16 + g;
        #pragma unroll
        for (int nf = 0; nf < 8; nf++) {
            int c = bn + wn + nf * 8 + 2 * tg;
            if (c + 1 < N) {
                *(float2*)&C[(int64_t)r0 * ldc + c] =
                    make_float2(acc[mf][nf][0], acc[mf][nf][1]);
                *(float2*)&C[(int64_t)(r0 + 8) * ldc + c] =
                    make_float2(acc[mf][nf][2], acc[mf][nf][3]);
            } else if (c < N) {
                C[(int64_t)r0 * ldc + c]       = acc[mf][nf][0];
                C[(int64_t)(r0 + 8) * ldc + c] = acc[mf][nf][2];
            }
        }
    }
}

// ---------------- launch ----------------
extern "C" void kernel_launch(void* const* d_in, const int* in_sizes, int n_in,
                              void* d_out, int out_size) {
    const float* x  = (const float*)d_in[0];  // [8192, 4096]
    const float* W0 = (const float*)d_in[1];  // [4096, 4096]
    const float* Wg = (const float*)d_in[2];  // [8, 4096]
    const float* A  = (const float*)d_in[3];  // [8, 16, 4096]
    const float* B  = (const float*)d_in[4];  // [8, 4096, 16]
    float* out = (float*)d_out;               // [8192, 4096]

    __half *Xcat, *Wcat, *WgA;
    float* P;
    cudaGetSymbolAddress((void**)&Xcat, g_Xcat);
    cudaGetSymbolAddress((void**)&Wcat, g_Wcat);
    cudaGetSymbolAddress((void**)&WgA,  g_WgA);
    cudaGetSymbolAddress((void**)&P,    g_P);

    conv_x_kernel   <<<2048, 256>>>((const float4*)x, Xcat);
    conv_w0_kernel  <<<2048, 256>>>((const float4*)W0, Wcat);
    conv_bmat_kernel<<<512,  256>>>(B, Wcat);
    conv_wga_kernel <<<512,  256>>>(Wg, A, WgA);

    // P[8192,136] = x_fp16 @ [Wg;A]^T   (K = 4096, A operand strided by KCAT)
    gemm_f16_pipe<<<dim3(2, NROWS / BM), 256>>>(
        Xcat, WgA, P, NROWS, P_COLS, IN_F, KCAT, IN_F, P_COLS);

    // softmax gate, scale, pack H into Xcat[:, 4096:4224]
    softmax_pack_kernel<<<NROWS, 128>>>(P, Xcat);

    // out = [x | H] @ [W0 | Bmat]^T   (K = 4224)
    gemm_f16_pipe<<<dim3(OUT_F / BN, NROWS / BM), 256>>>(
        Xcat, Wcat, out, NROWS, OUT_F, KCAT, KCAT, KCAT, OUT_F);
}

// round 7
// speedup vs baseline: 1.4547x; 1.0322x over previous
#include <cuda_runtime.h>
#include <cuda_fp16.h>
#include <cstdint>

// Problem constants
#define NROWS   8192
#define IN_F    4096
#define OUT_F   4096
#define E_NUM   8
#define R_PER   16
#define R_TOT   128              // E_NUM * R_PER
#define KCAT    (IN_F + R_TOT)   // 4224
#define P_COLS  (E_NUM + R_TOT)  // 136
#define SCALING 0.125f           // 16 / 128
#define KSPLIT  4                // split-K for skinny gate GEMM

// -------- device scratch (allocation-free rule: __device__ globals) --------
__device__ __align__(1024) __half g_Xcat[(size_t)NROWS * KCAT];  // [8192,4224] [x | H]
__device__ __align__(1024) __half g_Wcat[(size_t)OUT_F * KCAT];  // [4096,4224] [W0 | Bmat]
__device__ __align__(1024) __half g_WgA [(size_t)P_COLS * IN_F]; // [136,4096]  [Wg ; A]
__device__ float g_P[(size_t)KSPLIT * NROWS * P_COLS];           // split-K partials

__device__ __forceinline__ uint32_t smem_u32(const void* p) {
    return (uint32_t)__cvta_generic_to_shared(p);
}

// ===================== conversion kernels =====================
__global__ void conv_x_kernel(const float4* __restrict__ x, __half* __restrict__ Xcat) {
    int64_t total = (int64_t)NROWS * IN_F / 4;
    for (int64_t i = (int64_t)blockIdx.x * blockDim.x + threadIdx.x; i < total;
         i += (int64_t)gridDim.x * blockDim.x) {
        float4 v = x[i];
        int64_t e = i << 2;
        int n = (int)(e >> 12);
        int k = (int)(e & 4095);
        __half2* dst = (__half2*)&Xcat[(int64_t)n * KCAT + k];
        dst[0] = __floats2half2_rn(v.x, v.y);
        dst[1] = __floats2half2_rn(v.z, v.w);
    }
}

__global__ void conv_w0_kernel(const float4* __restrict__ W0, __half* __restrict__ Wcat) {
    int64_t total = (int64_t)OUT_F * IN_F / 4;
    for (int64_t i = (int64_t)blockIdx.x * blockDim.x + threadIdx.x; i < total;
         i += (int64_t)gridDim.x * blockDim.x) {
        float4 v = W0[i];
        int64_t e = i << 2;
        int o = (int)(e >> 12);
        int c = (int)(e & 4095);
        __half2* dst = (__half2*)&Wcat[(int64_t)o * KCAT + c];
        dst[0] = __floats2half2_rn(v.x, v.y);
        dst[1] = __floats2half2_rn(v.z, v.w);
    }
}

__global__ void conv_bmat_kernel(const float* __restrict__ B, __half* __restrict__ Wcat) {
    int64_t total = (int64_t)OUT_F * R_TOT;
    for (int64_t i = (int64_t)blockIdx.x * blockDim.x + threadIdx.x; i < total;
         i += (int64_t)gridDim.x * blockDim.x) {
        int o  = (int)(i >> 7);
        int cc = (int)(i & 127);
        int e = cc >> 4, r = cc & 15;
        Wcat[(int64_t)o * KCAT + IN_F + cc] =
            __float2half_rn(B[((int64_t)e * OUT_F + o) * R_PER + r]);
    }
}

__global__ void conv_wga_kernel(const float* __restrict__ Wg, const float* __restrict__ A,
                                __half* __restrict__ WgA) {
    int64_t total = (int64_t)P_COLS * IN_F;
    for (int64_t i = (int64_t)blockIdx.x * blockDim.x + threadIdx.x; i < total;
         i += (int64_t)gridDim.x * blockDim.x) {
        int j = (int)(i >> 12);
        int k = (int)(i & 4095);
        float v = (j < E_NUM) ? Wg[(int64_t)j * IN_F + k]
                              : A[(int64_t)(j - E_NUM) * IN_F + k];
        WgA[i] = __float2half_rn(v);
    }
}

// ======= softmax + split-K reduce + pack H into Xcat =======
__global__ void softmax_pack_kernel(const float* __restrict__ P, __half* __restrict__ Xcat) {
    int n = blockIdx.x;
    int t = threadIdx.x;
    __shared__ float gate[E_NUM];
    const int64_t zs = (int64_t)NROWS * P_COLS;
    if (t == 0) {
        float l[E_NUM];
        float mx = -1e30f;
        #pragma unroll
        for (int e = 0; e < E_NUM; e++) {
            float s = 0.f;
            #pragma unroll
            for (int z = 0; z < KSPLIT; z++) s += P[z * zs + (int64_t)n * P_COLS + e];
            l[e] = s; mx = fmaxf(mx, s);
        }
        float s = 0.f;
        #pragma unroll
        for (int e = 0; e < E_NUM; e++) { l[e] = expf(l[e] - mx); s += l[e]; }
        float inv = 1.0f / s;
        #pragma unroll
        for (int e = 0; e < E_NUM; e++) gate[e] = l[e] * inv;
    }
    __syncthreads();
    float h = 0.f;
    #pragma unroll
    for (int z = 0; z < KSPLIT; z++) h += P[z * zs + (int64_t)n * P_COLS + E_NUM + t];
    int e = t >> 4;
    Xcat[(int64_t)n * KCAT + IN_F + t] = __float2half_rn(SCALING * gate[e] * h);
}

// ============ fp16 mma.sync GEMM, 5-stage cp.async multistage + ldmatrix ============
// C_z[M,N] = A[:, zoff : zoff+K] @ B[:, zoff : zoff+K]^T   (zoff = blockIdx.z * K)
#define BM 128
#define BN 128
#define BK 32
#define SLD 40        // BK + 8 halves padding -> conflict-free ldmatrix
#define STG 5         // pipeline stages (4 tiles in flight)
#define STAGE_HALVES (BM * SLD)          // per-operand per-stage halves (5120)
#define DYN_SMEM (2 * STG * STAGE_HALVES * 2)  // bytes = 102400

__device__ __forceinline__ void cp16(uint32_t dst, const void* src, bool pred) {
    int sz = pred ? 16 : 0;   // src-size 0 -> zero-fill
    asm volatile("cp.async.cg.shared.global [%0], [%1], 16, %2;\n" :: "r"(dst), "l"(src), "r"(sz));
}
__device__ __forceinline__ void ldsm_x4(uint32_t& r0, uint32_t& r1, uint32_t& r2, uint32_t& r3,
                                        uint32_t addr) {
    asm volatile("ldmatrix.sync.aligned.m8n8.x4.shared.b16 {%0,%1,%2,%3}, [%4];\n"
                 : "=r"(r0), "=r"(r1), "=r"(r2), "=r"(r3) : "r"(addr));
}

__global__ __launch_bounds__(256, 2)
void gemm_f16_ms(const __half* __restrict__ A, const __half* __restrict__ B,
                 float* __restrict__ C,
                 int M, int N, int K, int lda, int ldb, int ldc) {
    extern __shared__ __half sm[];
    __half* As = sm;                          // [STG][BM*SLD]
    __half* Bs = sm + STG * STAGE_HALVES;     // [STG][BN*SLD]

    const int tid  = threadIdx.x;
    const int warp = tid >> 5;
    const int lane = tid & 31;
    const int g    = lane >> 2;
    const int tg   = lane & 3;
    const int lm   = lane & 7;
    const int wm   = (warp & 3) * 32;   // 4 warps along M
    const int wn   = (warp >> 2) * 64;  // 2 warps along N
    const int bm   = blockIdx.y * BM;
    const int bn   = blockIdx.x * BN;
    const int zoff = blockIdx.z * K;
    float* Cz = C + (int64_t)blockIdx.z * (int64_t)M * ldc;

    const int lr = tid >> 2;
    const int lc = (tid & 3) * 8;

    float acc[2][8][4];
    #pragma unroll
    for (int mf = 0; mf < 2; mf++)
        #pragma unroll
        for (int nf = 0; nf < 8; nf++)
            #pragma unroll
            for (int i = 0; i < 4; i++) acc[mf][nf][i] = 0.f;

    const int nt = K / BK;
    const int a_row_off = ((lane >> 3) & 1) * 8 + lm;
    const int a_col_off = (lane >> 4) * 8;
    const int b_row_off = (lane >> 4) * 8 + lm;
    const int b_col_off = ((lane >> 3) & 1) * 8;

    auto load_stage = [&](int s, int k0) {
        __half* Ast = As + s * STAGE_HALVES;
        __half* Bst = Bs + s * STAGE_HALVES;
        #pragma unroll
        for (int i = 0; i < 2; i++) {
            int row = lr + i * 64;
            cp16(smem_u32(&Ast[row * SLD + lc]),
                 A + (int64_t)(bm + row) * lda + zoff + k0 + lc, true);
        }
        #pragma unroll
        for (int i = 0; i < 2; i++) {
            int row = lr + i * 64;
            cp16(smem_u32(&Bst[row * SLD + lc]),
                 B + (int64_t)(bn + row) * ldb + zoff + k0 + lc, (bn + row) < N);
        }
        asm volatile("cp.async.commit_group;\n");
    };

    // prologue: fill STG-1 stages
    #pragma unroll
    for (int s = 0; s < STG - 1; s++) load_stage(s, s * BK);

    for (int t = 0; t < nt; t++) {
        const int s = t % STG;
        asm volatile("cp.async.wait_group %0;\n" :: "n"(STG - 2));
        __syncthreads();

        // refill: stage (t-1)%STG == (t+STG-1)%STG, finished by all warps last iter
        int tn = t + STG - 1;
        if (tn < nt) load_stage(tn % STG, tn * BK);

        const __half* Ast = As + s * STAGE_HALVES;
        const __half* Bst = Bs + s * STAGE_HALVES;
        #pragma unroll
        for (int kk = 0; kk < BK; kk += 16) {
            uint32_t a[2][4], b[8][2];
            #pragma unroll
            for (int mf = 0; mf < 2; mf++) {
                uint32_t addr = smem_u32(&Ast[(wm + mf * 16 + a_row_off) * SLD + kk + a_col_off]);
                ldsm_x4(a[mf][0], a[mf][1], a[mf][2], a[mf][3], addr);
            }
            #pragma unroll
            for (int p = 0; p < 4; p++) {
                uint32_t addr = smem_u32(&Bst[(wn + p * 16 + b_row_off) * SLD + kk + b_col_off]);
                ldsm_x4(b[2 * p][0], b[2 * p][1], b[2 * p + 1][0], b[2 * p + 1][1], addr);
            }
            #pragma unroll
            for (int mf = 0; mf < 2; mf++)
                #pragma unroll
                for (int nf = 0; nf < 8; nf++)
                    asm volatile(
                        "mma.sync.aligned.m16n8k16.row.col.f32.f16.f16.f32 "
                        "{%0,%1,%2,%3}, {%4,%5,%6,%7}, {%8,%9}, {%0,%1,%2,%3};\n"
                        : "+f"(acc[mf][nf][0]), "+f"(acc[mf][nf][1]),
                          "+f"(acc[mf][nf][2]), "+f"(acc[mf][nf][3])
                        : "r"(a[mf][0]), "r"(a[mf][1]), "r"(a[mf][2]), "r"(a[mf][3]),
                          "r"(b[nf][0]), "r"(b[nf][1]));
        }
        __syncthreads();
    }

    #pragma unroll
    for (int mf = 0; mf < 2; mf++) {
        int r0 = bm + wm + mf * 16 + g;
        #pragma unroll
        for (int nf = 0; nf < 8; nf++) {
            int c = bn + wn + nf * 8 + 2 * tg;
            if (c + 1 < N) {
                *(float2*)&Cz[(int64_t)r0 * ldc + c] = make_float2(acc[mf][nf][0], acc[mf][nf][1]);
                *(float2*)&Cz[(int64_t)(r0 + 8) * ldc + c] = make_float2(acc[mf][nf][2], acc[mf][nf][3]);
            } else if (c < N) {
                Cz[(int64_t)r0 * ldc + c]       = acc[mf][nf][0];
                Cz[(int64_t)(r0 + 8) * ldc + c] = acc[mf][nf][2];
            }
        }
    }
}

// ===================== launch =====================
extern "C" void kernel_launch(void* const* d_in, const int* in_sizes, int n_in,
                              void* d_out, int out_size) {
    const float* x  = (const float*)d_in[0];  // [8192, 4096]
    const float* W0 = (const float*)d_in[1];  // [4096, 4096]
    const float* Wg = (const float*)d_in[2];  // [8, 4096]
    const float* A  = (const float*)d_in[3];  // [8, 16, 4096]
    const float* B  = (const float*)d_in[4];  // [8, 4096, 16]
    float* out = (float*)d_out;               // [8192, 4096]

    __half *Xcat, *Wcat, *WgA;
    float* P;
    cudaGetSymbolAddress((void**)&Xcat, g_Xcat);
    cudaGetSymbolAddress((void**)&Wcat, g_Wcat);
    cudaGetSymbolAddress((void**)&WgA,  g_WgA);
    cudaGetSymbolAddress((void**)&P,    g_P);

    static bool attr_set = false;
    if (!attr_set) {
        cudaFuncSetAttribute(gemm_f16_ms, cudaFuncAttributeMaxDynamicSharedMemorySize, DYN_SMEM);
        attr_set = true;
    }

    // conversions
    conv_x_kernel   <<<2048, 256>>>((const float4*)x, Xcat);
    conv_w0_kernel  <<<2048, 256>>>((const float4*)W0, Wcat);
    conv_bmat_kernel<<<512,  256>>>(B, Wcat);
    conv_wga_kernel <<<512,  256>>>(Wg, A, WgA);

    // skinny gate GEMM, split-K=4: P[z] = x_fp16[:, z*1024:(z+1)*1024] @ [Wg;A]^T
    gemm_f16_ms<<<dim3(2, NROWS / BM, KSPLIT), 256, DYN_SMEM>>>(
        Xcat, WgA, P, NROWS, P_COLS, IN_F / KSPLIT, KCAT, IN_F, P_COLS);

    // softmax gate + split-K reduce + pack H into Xcat[:, 4096:4224]
    softmax_pack_kernel<<<NROWS, 128>>>(P, Xcat);

    // main GEMM: out = [x | H] @ [W0 | Bmat]^T
    gemm_f16_ms<<<dim3(OUT_F / BN, NROWS / BM, 1), 256, DYN_SMEM>>>(
        Xcat, Wcat, out, NROWS, OUT_F, KCAT, KCAT, KCAT, OUT_F);
}